// round 4
// baseline (speedup 1.0000x reference)
#include <cuda_runtime.h>
#include <cstdint>

#define NB   16384
#define NPG  9
#define RK   512
#define EPG  12
#define NN   (NB*NPG)

// ---------------- scratch (static device globals; no runtime allocation) ----
__device__ float g_m[(size_t)NN*RK];      // aggregated GEMM input (tf32, k-permuted)
__device__ float g_h[(size_t)NN*RK];      // GEMM output (normal order)
__device__ float g_mc[(size_t)NB*RK];     // compact layer-3 input (k-permuted)
__device__ float g_hc[(size_t)NB*RK];     // compact layer-3 output
__device__ float g_Wt[3*RK*RK];           // tf32 W, transposed [N][K], k-permuted
__device__ int   g_src64;
__device__ int   g_feat64;

// k-permutation within each 8-group: stored position of k is (k&~7)|((k&3)<<1)|((k&7)>>2)
// inverse: position p holds k = (p&~7) + ((p&7)>>1) + (p&1)*4
__device__ __forceinline__ int kperm(int k){
    return (k & ~7) | ((k & 3) << 1) | ((k & 7) >> 2);
}

// ---------------- helpers ---------------------------------------------------
__device__ __forceinline__ float tf32r(float x){
    unsigned u; asm("cvt.rna.tf32.f32 %0, %1;" : "=r"(u) : "f"(x));
    return __uint_as_float(u);
}
__device__ __forceinline__ float wredsum(float v){
    #pragma unroll
    for (int o = 16; o; o >>= 1) v += __shfl_xor_sync(0xffffffffu, v, o);
    return v;
}
__device__ __forceinline__ void cp_async16(void* smem, const void* g){
    unsigned s = (unsigned)__cvta_generic_to_shared(smem);
    asm volatile("cp.async.cg.shared.global [%0], [%1], 16;\n" :: "r"(s), "l"(g));
}
__device__ __forceinline__ void cp_commit(){ asm volatile("cp.async.commit_group;\n"); }
template<int W> __device__ __forceinline__ void cp_wait(){
    asm volatile("cp.async.wait_group %0;\n" :: "n"(W));
}
__device__ __forceinline__ void mma_tf32(float* c, const unsigned* a, const unsigned* b){
    asm volatile(
        "mma.sync.aligned.m16n8k8.row.col.f32.tf32.tf32.f32 "
        "{%0,%1,%2,%3},{%4,%5,%6,%7},{%8,%9},{%0,%1,%2,%3};\n"
        : "+f"(c[0]), "+f"(c[1]), "+f"(c[2]), "+f"(c[3])
        : "r"(a[0]), "r"(a[1]), "r"(a[2]), "r"(a[3]), "r"(b[0]), "r"(b[1]));
}
__device__ __forceinline__ int read_idx(const void* p, int is64, long long i){
    return is64 ? (int)((const long long*)p)[i] : ((const int*)p)[i];
}

// ---------------- dtype detection (int32 vs int64 indices) -------------------
__global__ void detect_kernel(const int* sw, const int* fw){
    const int t = threadIdx.x;
    unsigned s = __ballot_sync(0xffffffffu, sw[2*t+1] != 0);
    unsigned f = __ballot_sync(0xffffffffu, fw[2*t+1] != 0);
    if (t == 0){ g_src64 = (s == 0); g_feat64 = (f == 0); }
}

// ------ transpose + tf32 + permute W: g_Wt[n][perm(k)] = tf32(Ws[k][n]) -----
__global__ void round_w_kernel(const float* __restrict__ Ws){
    __shared__ float t[32][33];
    const int L = blockIdx.z;
    const int k0 = blockIdx.x*32, n0 = blockIdx.y*32;
    const float* src = Ws + (size_t)L*RK*RK;
    for (int i = threadIdx.y; i < 32; i += 8)
        t[i][threadIdx.x] = src[(size_t)(k0+i)*RK + n0 + threadIdx.x];
    __syncthreads();
    float* dst = g_Wt + (size_t)L*RK*RK;
    for (int i = threadIdx.y; i < 32; i += 8)
        dst[(size_t)(n0+i)*RK + k0 + kperm(threadIdx.x)] = tf32r(t[threadIdx.x][i]);
}

// ---- permuted float4 writer: chunk c4 covers stored positions 4*c4..+3 -----
// sources: k0 = 8*(c4>>1) + 2*(c4&1);  ks = {k0, k0+4, k0+1, k0+5}
__device__ __forceinline__ void store_perm4(float* dst, const float* row,
                                            int c4, float scale){
    const int k0 = ((c4 >> 1) << 3) + ((c4 & 1) << 1);
    float4 v;
    v.x = tf32r(row[k0    ]*scale);
    v.y = tf32r(row[k0 + 4]*scale);
    v.z = tf32r(row[k0 + 1]*scale);
    v.w = tf32r(row[k0 + 5]*scale);
    ((float4*)dst)[c4] = v;
}

// ---------------- layer-0 aggregation: emb gather + norm + scatter-add ------
__global__ __launch_bounds__(256) void agg0_kernel(
    const void* __restrict__ featp, const void* __restrict__ srcp,
    const void* __restrict__ dstp, const float* __restrict__ emb)
{
    __shared__ float hs[NPG][RK];
    __shared__ float ms[NPG][RK];
    __shared__ int sl[EPG], dl[EPG], odeg[NPG], ideg[NPG], feats[NPG];
    __shared__ float onrm[NPG], inrm[NPG];
    const int g = blockIdx.x, tid = threadIdx.x;
    const int f64 = g_feat64, s64 = g_src64;

    if (tid < NPG){
        odeg[tid] = 0; ideg[tid] = 0;
        feats[tid] = read_idx(featp, f64, (long long)g*NPG + tid);
    }
    __syncthreads();
    if (tid < EPG){
        long long e = (long long)g*EPG + tid;
        int s = read_idx(srcp, s64, e) - g*NPG;
        int d = read_idx(dstp, s64, e) - g*NPG;
        sl[tid] = s; dl[tid] = d;
        atomicAdd(&odeg[s], 1); atomicAdd(&ideg[d], 1);
    }
    for (int idx = tid; idx < NPG*(RK/4); idx += 256){
        int i = idx/(RK/4), c4 = idx%(RK/4);
        float4 v = ((const float4*)(emb + (size_t)feats[i]*RK))[c4];
        ((float4*)&hs[i][0])[c4] = v;
        ((float4*)&ms[i][0])[c4] = make_float4(0.f,0.f,0.f,0.f);
    }
    __syncthreads();
    if (tid < NPG){
        onrm[tid] = odeg[tid] ? rsqrtf((float)odeg[tid]) : 1.0f;
        inrm[tid] = ideg[tid] ? rsqrtf((float)ideg[tid]) : 1.0f;
    }
    __syncthreads();
    const int f0 = tid, f1 = tid + 256;
    #pragma unroll
    for (int e = 0; e < EPG; e++){
        int s = sl[e], d = dl[e];
        float w = onrm[s];
        ms[d][f0] += hs[s][f0]*w;
        ms[d][f1] += hs[s][f1]*w;
    }
    __syncthreads();
    float* Mg = g_m + (size_t)g*NPG*RK;
    for (int idx = tid; idx < NPG*(RK/4); idx += 256){
        int i = idx/(RK/4), c4 = idx%(RK/4);
        store_perm4(Mg + (size_t)i*RK, &ms[i][0], c4, inrm[i]);
    }
}

// -------- fused bias + LN + ReLU (prev layer) + aggregation (this layer) ----
__global__ __launch_bounds__(256) void aggln_kernel(
    const void* __restrict__ srcp, const void* __restrict__ dstp,
    const float* __restrict__ bias, const float* __restrict__ gamma,
    const float* __restrict__ beta, float* __restrict__ mout, int compact)
{
    __shared__ float hs[NPG][RK];
    __shared__ float ms[NPG][RK];
    __shared__ float gsm[RK], btsm[RK];
    __shared__ int sl[EPG], dl[EPG], odeg[NPG], ideg[NPG];
    __shared__ float onrm[NPG], inrm[NPG], mu9[NPG], rs9[NPG];
    const int g = blockIdx.x, tid = threadIdx.x;
    const int s64 = g_src64;

    if (tid < NPG){ odeg[tid] = 0; ideg[tid] = 0; }
    for (int f = tid; f < RK; f += 256){ gsm[f] = gamma[f]; btsm[f] = beta[f]; }
    __syncthreads();
    if (tid < EPG){
        long long e = (long long)g*EPG + tid;
        int s = read_idx(srcp, s64, e) - g*NPG;
        int d = read_idx(dstp, s64, e) - g*NPG;
        sl[tid] = s; dl[tid] = d;
        atomicAdd(&odeg[s], 1); atomicAdd(&ideg[d], 1);
    }
    const float* Hg = g_h + (size_t)g*NPG*RK;
    for (int idx = tid; idx < NPG*(RK/4); idx += 256){
        int i = idx/(RK/4), c4 = idx%(RK/4);
        float4 v = ((const float4*)Hg)[idx];
        float4 b = ((const float4*)bias)[c4];
        v.x += b.x; v.y += b.y; v.z += b.z; v.w += b.w;
        ((float4*)&hs[i][0])[c4] = v;
    }
    __syncthreads();
    if (tid < NPG){
        onrm[tid] = odeg[tid] ? rsqrtf((float)odeg[tid]) : 1.0f;
        inrm[tid] = ideg[tid] ? rsqrtf((float)ideg[tid]) : 1.0f;
    }
    const int w = tid >> 5, ln = tid & 31;
    for (int r = w; r < NPG; r += 8){
        float s = 0.f, ss = 0.f;
        #pragma unroll
        for (int j = 0; j < RK/32; j++){ float v = hs[r][ln + j*32]; s += v; ss += v*v; }
        s = wredsum(s); ss = wredsum(ss);
        if (ln == 0){
            float mu = s*(1.0f/RK);
            mu9[r] = mu;
            rs9[r] = rsqrtf(ss*(1.0f/RK) - mu*mu + 1e-5f);
        }
    }
    __syncthreads();
    for (int idx = tid; idx < NPG*RK; idx += 256){
        int i = idx >> 9, f = idx & (RK-1);
        float v = (hs[i][f] - mu9[i])*rs9[i]*gsm[f] + btsm[f];
        hs[i][f] = fmaxf(v, 0.f)*onrm[i];
        ms[i][f] = 0.f;
    }
    __syncthreads();
    const int f0 = tid, f1 = tid + 256;
    #pragma unroll
    for (int e = 0; e < EPG; e++){
        int s = sl[e], d = dl[e];
        ms[d][f0] += hs[s][f0];
        ms[d][f1] += hs[s][f1];
    }
    __syncthreads();
    if (compact){
        float* Mg = mout + (size_t)g*RK;
        for (int c4 = tid; c4 < RK/4; c4 += 256)
            store_perm4(Mg, &ms[0][0], c4, inrm[0]);
    } else {
        float* Mg = mout + (size_t)g*NPG*RK;
        for (int idx = tid; idx < NPG*(RK/4); idx += 256){
            int i = idx/(RK/4), c4 = idx%(RK/4);
            store_perm4(Mg + (size_t)i*RK, &ms[i][0], c4, inrm[i]);
        }
    }
}

// ------------- TF32 GEMM: C = A @ W^T  A:[M,512] perm-k, W^T:[512,512] ------
// CTA 128x256, warp grid 2x4, warp tile 64x64; 3-stage cp.async; LDS.64 frags.
#define BM 128
#define BN 256
#define BK 32
#define APITCH 40
#define BPITCH 40
#define STAGES 3
#define STG_F (BM*APITCH + BN*BPITCH)        // 15360 floats / stage
#define SMEM_GEMM (STAGES*STG_F*4)           // 184320 B

__global__ __launch_bounds__(256,1) void gemm_tf32_kernel(
    const float* __restrict__ A, const float* __restrict__ Wt,
    float* __restrict__ C)
{
    extern __shared__ float smbuf[];
    const int tid = threadIdx.x;
    const int bn = blockIdx.x, bm = blockIdx.y;
    const int lane = tid & 31, warp = tid >> 5;
    const int wm = warp & 1, wn = warp >> 1;     // 2 (M) x 4 (N)
    const int gid = lane >> 2, tig = lane & 3;

    float c[4][8][4];
    #pragma unroll
    for (int mt = 0; mt < 4; mt++)
        #pragma unroll
        for (int nf = 0; nf < 8; nf++)
            #pragma unroll
            for (int q = 0; q < 4; q++) c[mt][nf][q] = 0.f;

    const float* Ag = A  + (size_t)bm*BM*RK;
    const float* Bg = Wt + (size_t)bn*BN*RK;

    auto fill = [&](int t){
        float* As = smbuf + (t % STAGES)*STG_F;
        float* Bs = As + BM*APITCH;
        const int k0 = t*BK;
        #pragma unroll
        for (int i = 0; i < 4; i++){           // A: 128 rows x 8 chunks
            int idx = tid + i*256; int r = idx >> 3, cc = idx & 7;
            cp_async16(&As[r*APITCH + cc*4], Ag + (size_t)r*RK + k0 + cc*4);
        }
        #pragma unroll
        for (int i = 0; i < 8; i++){           // B: 256 rows x 8 chunks
            int idx = tid + i*256; int r = idx >> 3, cc = idx & 7;
            cp_async16(&Bs[r*BPITCH + cc*4], Bg + (size_t)r*RK + k0 + cc*4);
        }
        cp_commit();
    };

    fill(0); fill(1);

    #pragma unroll 1
    for (int kt = 0; kt < RK/BK; kt++){
        cp_wait<1>();
        __syncthreads();
        if (kt + 2 < RK/BK) fill(kt + 2);
        else cp_commit();

        const float* Ac = smbuf + (kt % STAGES)*STG_F;
        const float* Bc = Ac + BM*APITCH;
        #pragma unroll
        for (int ks = 0; ks < BK/8; ks++){
            const int kp = ks*8 + 2*tig;       // paired fragment base (perm layout)
            unsigned a[4][4]; unsigned b[8][2];
            #pragma unroll
            for (int mt = 0; mt < 4; mt++){
                int r = wm*64 + mt*16 + gid;
                float2 p0 = *(const float2*)&Ac[ r    *APITCH + kp];  // (a0,a2)
                float2 p1 = *(const float2*)&Ac[(r+8) *APITCH + kp];  // (a1,a3)
                a[mt][0] = __float_as_uint(p0.x);
                a[mt][1] = __float_as_uint(p1.x);
                a[mt][2] = __float_as_uint(p0.y);
                a[mt][3] = __float_as_uint(p1.y);
            }
            #pragma unroll
            for (int nf = 0; nf < 8; nf++){
                int cn = wn*64 + nf*8 + gid;
                float2 pb = *(const float2*)&Bc[cn*BPITCH + kp];      // (b0,b1)
                b[nf][0] = __float_as_uint(pb.x);
                b[nf][1] = __float_as_uint(pb.y);
            }
            #pragma unroll
            for (int mt = 0; mt < 4; mt++)
                #pragma unroll
                for (int nf = 0; nf < 8; nf++)
                    mma_tf32(c[mt][nf], a[mt], b[nf]);
        }
    }
    #pragma unroll
    for (int mt = 0; mt < 4; mt++){
        int r = bm*BM + wm*64 + mt*16 + gid;
        #pragma unroll
        for (int nf = 0; nf < 8; nf++){
            int cn = bn*BN + wn*64 + nf*8 + tig*2;
            *(float2*)&C[(size_t)r*RK + cn]     = make_float2(c[mt][nf][0], c[mt][nf][1]);
            *(float2*)&C[(size_t)(r+8)*RK + cn] = make_float2(c[mt][nf][2], c[mt][nf][3]);
        }
    }
}

// ---------------- output head: bias + LN + ReLU on compact rows, dot w_out --
__global__ __launch_bounds__(256) void out_kernel(
    const float* __restrict__ bias, const float* __restrict__ gamma,
    const float* __restrict__ beta, const float* __restrict__ wout,
    const float* __restrict__ bout, float* __restrict__ out)
{
    const int g = blockIdx.x*8 + (threadIdx.x >> 5);
    const int ln = threadIdx.x & 31;
    const float* row = g_hc + (size_t)g*RK;
    float v[16]; float s = 0.f, ss = 0.f;
    #pragma unroll
    for (int j = 0; j < 16; j++){
        int f = ln + j*32;
        float x = row[f] + bias[f];
        v[j] = x; s += x; ss += x*x;
    }
    s = wredsum(s); ss = wredsum(ss);
    float mu = s*(1.0f/RK);
    float rs = rsqrtf(ss*(1.0f/RK) - mu*mu + 1e-5f);
    float dot = 0.f;
    #pragma unroll
    for (int j = 0; j < 16; j++){
        int f = ln + j*32;
        float y = fmaxf((v[j]-mu)*rs*gamma[f] + beta[f], 0.f);
        dot += y*wout[f];
    }
    dot = wredsum(dot);
    if (ln == 0) out[g] = dot + bout[0];
}

// ---------------- launcher ---------------------------------------------------
extern "C" void kernel_launch(void* const* d_in, const int* in_sizes, int n_in,
                              void* d_out, int out_size){
    (void)in_sizes; (void)n_in; (void)out_size;
    const void*  feat = d_in[0];
    const void*  src  = d_in[1];
    const void*  dst  = d_in[2];
    const float* emb  = (const float*)d_in[3];
    const float* Ws   = (const float*)d_in[4];
    const float* bs   = (const float*)d_in[5];
    const float* gam  = (const float*)d_in[6];
    const float* bet  = (const float*)d_in[7];
    const float* wout = (const float*)d_in[8];
    const float* bout = (const float*)d_in[9];
    float* out = (float*)d_out;

    cudaFuncSetAttribute(gemm_tf32_kernel,
                         cudaFuncAttributeMaxDynamicSharedMemorySize, SMEM_GEMM);

    float* gm;  cudaGetSymbolAddress((void**)&gm,  g_m);
    float* gh;  cudaGetSymbolAddress((void**)&gh,  g_h);
    float* gmc; cudaGetSymbolAddress((void**)&gmc, g_mc);
    float* ghc; cudaGetSymbolAddress((void**)&ghc, g_hc);
    float* gwt; cudaGetSymbolAddress((void**)&gwt, g_Wt);

    detect_kernel<<<1, 32>>>((const int*)src, (const int*)feat);
    round_w_kernel<<<dim3(16,16,3), dim3(32,8)>>>(Ws);

    agg0_kernel<<<NB, 256>>>(feat, src, dst, emb);
    dim3 gg(RK/BN, NN/BM);                 // (2, 1152)
    gemm_tf32_kernel<<<gg, 256, SMEM_GEMM>>>(gm, gwt, gh);
    aggln_kernel<<<NB, 256>>>(src, dst, bs,      gam,      bet,      gm,  0);
    gemm_tf32_kernel<<<gg, 256, SMEM_GEMM>>>(gm, gwt + RK*RK, gh);
    aggln_kernel<<<NB, 256>>>(src, dst, bs + RK, gam + RK, bet + RK, gmc, 1);
    dim3 gc(RK/BN, NB/BM);                 // (2, 128)
    gemm_tf32_kernel<<<gc, 256, SMEM_GEMM>>>(gmc, gwt + 2*RK*RK, ghc);
    out_kernel<<<NB/8, 256>>>(bs + 2*RK, gam + 2*RK, bet + 2*RK, wout, bout, out);
}

// round 5
// speedup vs baseline: 3.6322x; 3.6322x over previous
#include <cuda_runtime.h>
#include <cstdint>

#define NB   16384
#define NPG  9
#define RK   512
#define EPG  12
#define NN   (NB*NPG)
#define VOC  6

// ---------------- scratch (static device globals; zero-initialized) ---------
__device__ float g_m[(size_t)NN*RK];      // compact m1 rows (tf32, k-permuted)
__device__ float g_h[(size_t)NN*RK];      // compact h2 rows (GEMM1 out)
__device__ float g_mc[(size_t)NB*RK];     // layer-3 GEMM input (node0 rows)
__device__ float g_hc[(size_t)NB*RK];     // layer-3 GEMM output
__device__ float g_Wt[3*RK*RK];           // tf32 W, transposed [N][K], k-permuted
__device__ float g_EW0[VOC*RK];           // emb @ W0 (exact fp32)
__device__ int   g_cnt[NB];               // |S2| per graph
__device__ int   g_off[NB];               // exclusive prefix of g_cnt
__device__ int   g_lid[NN];               // local node id per compact row
__device__ int   g_total;
__device__ int   g_src64;
__device__ int   g_feat64;

// k-permutation within each 8-group (enables paired LDS.64 mma fragments)
__device__ __forceinline__ int kperm(int k){
    return (k & ~7) | ((k & 3) << 1) | ((k & 7) >> 2);
}

// ---------------- helpers ---------------------------------------------------
__device__ __forceinline__ float tf32r(float x){
    unsigned u; asm("cvt.rna.tf32.f32 %0, %1;" : "=r"(u) : "f"(x));
    return __uint_as_float(u);
}
__device__ __forceinline__ float wredsum(float v){
    #pragma unroll
    for (int o = 16; o; o >>= 1) v += __shfl_xor_sync(0xffffffffu, v, o);
    return v;
}
__device__ __forceinline__ void cp_async16(void* smem, const void* g){
    unsigned s = (unsigned)__cvta_generic_to_shared(smem);
    asm volatile("cp.async.cg.shared.global [%0], [%1], 16;\n" :: "r"(s), "l"(g));
}
__device__ __forceinline__ void cp_commit(){ asm volatile("cp.async.commit_group;\n"); }
template<int W> __device__ __forceinline__ void cp_wait(){
    asm volatile("cp.async.wait_group %0;\n" :: "n"(W));
}
__device__ __forceinline__ void mma_tf32(float* c, const unsigned* a, const unsigned* b){
    asm volatile(
        "mma.sync.aligned.m16n8k8.row.col.f32.tf32.tf32.f32 "
        "{%0,%1,%2,%3},{%4,%5,%6,%7},{%8,%9},{%0,%1,%2,%3};\n"
        : "+f"(c[0]), "+f"(c[1]), "+f"(c[2]), "+f"(c[3])
        : "r"(a[0]), "r"(a[1]), "r"(a[2]), "r"(a[3]), "r"(b[0]), "r"(b[1]));
}
__device__ __forceinline__ int read_idx(const void* p, int is64, long long i){
    return is64 ? (int)((const long long*)p)[i] : ((const int*)p)[i];
}

// ---------------- dtype detection -------------------------------------------
__global__ void detect_kernel(const int* sw, const int* fw){
    const int t = threadIdx.x;
    unsigned s = __ballot_sync(0xffffffffu, sw[2*t+1] != 0);
    unsigned f = __ballot_sync(0xffffffffu, fw[2*t+1] != 0);
    if (t == 0){ g_src64 = (s == 0); g_feat64 = (f == 0); }
}

// ------ transpose + tf32 + permute W: g_Wt[L][n][perm(k)] = tf32(Ws[L][k][n])
__global__ void round_w_kernel(const float* __restrict__ Ws){
    __shared__ float t[32][33];
    const int L = blockIdx.z;
    const int k0 = blockIdx.x*32, n0 = blockIdx.y*32;
    const float* src = Ws + (size_t)L*RK*RK;
    for (int i = threadIdx.y; i < 32; i += 8)
        t[i][threadIdx.x] = src[(size_t)(k0+i)*RK + n0 + threadIdx.x];
    __syncthreads();
    float* dst = g_Wt + (size_t)L*RK*RK;
    for (int i = threadIdx.y; i < 32; i += 8)
        dst[(size_t)(n0+i)*RK + k0 + kperm(threadIdx.x)] = tf32r(t[threadIdx.x][i]);
}

// ---------------- EW0 = emb @ W0 (exact fp32, 6x512) -------------------------
__global__ void ew0_kernel(const float* __restrict__ emb, const float* __restrict__ W0){
    const int v = blockIdx.x;
    const int f = blockIdx.y*256 + threadIdx.x;
    float acc = 0.f;
    for (int k = 0; k < RK; k++)
        acc = fmaf(emb[(size_t)v*RK + k], W0[(size_t)k*RK + f], acc);
    g_EW0[(size_t)v*RK + f] = acc;
}

// --------- count distinct in-neighbors of local node 0 per graph ------------
__global__ void cnt_kernel(const void* __restrict__ srcp, const void* __restrict__ dstp){
    const int g = blockIdx.x*256 + threadIdx.x;
    const int s64 = g_src64;
    unsigned seen = 0; int cnt = 0;
    #pragma unroll
    for (int e = 0; e < EPG; e++){
        long long idx = (long long)g*EPG + e;
        int d = read_idx(dstp, s64, idx) - g*NPG;
        if (d == 0){
            int s = read_idx(srcp, s64, idx) - g*NPG;
            if (!((seen >> s) & 1u)){ seen |= 1u << s; cnt++; }
        }
    }
    g_cnt[g] = cnt;
}

// ---------------- exclusive scan of g_cnt (single CTA) ------------------------
__global__ __launch_bounds__(1024) void scan_kernel(){
    __shared__ int wsums[32];
    const int t = threadIdx.x, lane = t & 31, w = t >> 5;
    int c[16]; int s = 0;
    #pragma unroll
    for (int i = 0; i < 16; i++){ c[i] = g_cnt[t*16 + i]; s += c[i]; }
    int incl = s;
    #pragma unroll
    for (int o = 1; o < 32; o <<= 1){
        int v = __shfl_up_sync(0xffffffffu, incl, o);
        if (lane >= o) incl += v;
    }
    if (lane == 31) wsums[w] = incl;
    __syncthreads();
    if (w == 0){
        int iw = wsums[lane];
        #pragma unroll
        for (int o = 1; o < 32; o <<= 1){
            int u = __shfl_up_sync(0xffffffffu, iw, o);
            if (lane >= o) iw += u;
        }
        wsums[lane] = iw;
    }
    __syncthreads();
    int run = ((w == 0) ? 0 : wsums[w-1]) + incl - s;
    #pragma unroll
    for (int i = 0; i < 16; i++){ g_off[t*16 + i] = run; run += c[i]; }
    if (t == 1023) g_total = run;
}

// ==== fuse1: per graph — coef, h1 (rank-6, fp32), LN, ReLU, aggregate S2 ====
__global__ __launch_bounds__(256) void fuse1_kernel(
    const void* __restrict__ featp, const void* __restrict__ srcp,
    const void* __restrict__ dstp, const float* __restrict__ b0,
    const float* __restrict__ gam0, const float* __restrict__ bet0)
{
    __shared__ float hs[NPG][RK];
    __shared__ float coef[NPG][VOC];
    __shared__ int sl[EPG], dl[EPG], odeg[NPG], ideg[NPG], feats[NPG];
    __shared__ float onrm[NPG], inrm[NPG], mu9[NPG], rs9[NPG];
    __shared__ int s2list[NPG], s2n[NPG], s2src[NPG][EPG], s2cnt;
    const int g = blockIdx.x, tid = threadIdx.x;
    const int f64 = g_feat64, s64 = g_src64;

    if (tid < NPG){
        odeg[tid] = 0; ideg[tid] = 0;
        feats[tid] = read_idx(featp, f64, (long long)g*NPG + tid);
    }
    __syncthreads();
    if (tid < EPG){
        long long e = (long long)g*EPG + tid;
        int s = read_idx(srcp, s64, e) - g*NPG;
        int d = read_idx(dstp, s64, e) - g*NPG;
        sl[tid] = s; dl[tid] = d;
        atomicAdd(&odeg[s], 1); atomicAdd(&ideg[d], 1);
    }
    __syncthreads();
    if (tid < NPG){
        onrm[tid] = odeg[tid] ? rsqrtf((float)odeg[tid]) : 1.0f;
        inrm[tid] = ideg[tid] ? rsqrtf((float)ideg[tid]) : 1.0f;
    }
    __syncthreads();
    if (tid < NPG*VOC){
        const int n = tid / VOC, v = tid % VOC;
        float c = 0.f;
        #pragma unroll
        for (int e = 0; e < EPG; e++)
            if (dl[e] == n && feats[sl[e]] == v) c += onrm[sl[e]];
        coef[n][v] = c * inrm[n];
    }
    if (tid == 0){
        int cnt = 0; unsigned seen = 0;
        #pragma unroll
        for (int e = 0; e < EPG; e++){
            if (dl[e] == 0){
                int s = sl[e];
                if (!((seen >> s) & 1u)){ seen |= 1u << s; s2list[cnt++] = s; }
            }
        }
        s2cnt = cnt;
        for (int j = 0; j < cnt; j++){
            int s = s2list[j], n = 0;
            #pragma unroll
            for (int e = 0; e < EPG; e++)
                if (dl[e] == s) s2src[j][n++] = sl[e];
            s2n[j] = n;
        }
    }
    __syncthreads();
    // h1 = coef @ EW0 + b0 (exact fp32)
    #pragma unroll
    for (int rep = 0; rep < 2; rep++){
        const int f = tid + rep*256;
        #pragma unroll
        for (int n = 0; n < NPG; n++){
            float acc = b0[f];
            #pragma unroll
            for (int v = 0; v < VOC; v++)
                acc = fmaf(coef[n][v], g_EW0[(size_t)v*RK + f], acc);
            hs[n][f] = acc;
        }
    }
    __syncthreads();
    const int w = tid >> 5, ln = tid & 31;
    for (int r = w; r < NPG; r += 8){
        float s = 0.f, ss = 0.f;
        #pragma unroll
        for (int j = 0; j < RK/32; j++){ float v = hs[r][ln + j*32]; s += v; ss += v*v; }
        s = wredsum(s); ss = wredsum(ss);
        if (ln == 0){
            float mu = s*(1.0f/RK);
            mu9[r] = mu;
            rs9[r] = rsqrtf(ss*(1.0f/RK) - mu*mu + 1e-5f);
        }
    }
    __syncthreads();
    for (int idx = tid; idx < NPG*RK; idx += 256){
        int i = idx >> 9, f = idx & (RK-1);
        float v = (hs[i][f] - mu9[i])*rs9[i]*gam0[f] + bet0[f];
        hs[i][f] = fmaxf(v, 0.f)*onrm[i];
    }
    __syncthreads();
    // write compact m1 rows (tf32, k-permuted) for S2 nodes
    const int cnt = s2cnt, off = g_off[g];
    for (int j = 0; j < cnt; j++){
        const int s = s2list[j];
        const float sc = inrm[s];
        float* dst = g_m + (size_t)(off + j)*RK;
        const int nin = s2n[j];
        for (int c4 = tid; c4 < RK/4; c4 += 256){
            const int k0 = ((c4 >> 1) << 3) + ((c4 & 1) << 1);
            const int ks[4] = {k0, k0+4, k0+1, k0+5};
            float4 v;
            float* vp = &v.x;
            #pragma unroll
            for (int q = 0; q < 4; q++){
                float val = 0.f;
                for (int i = 0; i < nin; i++) val += hs[s2src[j][i]][ks[q]];
                vp[q] = tf32r(val*sc);
            }
            ((float4*)dst)[c4] = v;
        }
        if (tid == 0) g_lid[off + j] = s;
    }
}

// ==== fuseD: per graph — bias+LN+ReLU on compact h2 rows, build m2[0] ========
__global__ __launch_bounds__(256) void fuseD_kernel(
    const void* __restrict__ srcp, const void* __restrict__ dstp,
    const float* __restrict__ b1, const float* __restrict__ gam1,
    const float* __restrict__ bet1)
{
    __shared__ float hs[NPG][RK];
    __shared__ int sl[EPG], dl[EPG], odeg[NPG], ideg[NPG];
    __shared__ float onrm[NPG], mu9[NPG], rs9[NPG];
    __shared__ int lid[NPG], n2r[NPG];
    const int g = blockIdx.x, tid = threadIdx.x;
    const int s64 = g_src64;
    const int cnt = g_cnt[g], off = g_off[g];

    if (tid < NPG){ odeg[tid] = 0; ideg[tid] = 0; n2r[tid] = -1; }
    __syncthreads();
    if (tid < EPG){
        long long e = (long long)g*EPG + tid;
        int s = read_idx(srcp, s64, e) - g*NPG;
        int d = read_idx(dstp, s64, e) - g*NPG;
        sl[tid] = s; dl[tid] = d;
        atomicAdd(&odeg[s], 1); atomicAdd(&ideg[d], 1);
    }
    __syncthreads();
    if (tid < NPG)
        onrm[tid] = odeg[tid] ? rsqrtf((float)odeg[tid]) : 1.0f;
    if (tid < cnt){
        int s = g_lid[off + tid];
        lid[tid] = s; n2r[s] = tid;
    }
    __syncthreads();
    for (int idx = tid; idx < cnt*(RK/4); idx += 256){
        int j = idx/(RK/4), c4 = idx%(RK/4);
        float4 v = ((const float4*)(g_h + (size_t)(off + j)*RK))[c4];
        float4 b = ((const float4*)b1)[c4];
        v.x += b.x; v.y += b.y; v.z += b.z; v.w += b.w;
        ((float4*)&hs[j][0])[c4] = v;
    }
    __syncthreads();
    const int w = tid >> 5, ln = tid & 31;
    for (int r = w; r < cnt; r += 8){
        float s = 0.f, ss = 0.f;
        #pragma unroll
        for (int j = 0; j < RK/32; j++){ float v = hs[r][ln + j*32]; s += v; ss += v*v; }
        s = wredsum(s); ss = wredsum(ss);
        if (ln == 0){
            float mu = s*(1.0f/RK);
            mu9[r] = mu;
            rs9[r] = rsqrtf(ss*(1.0f/RK) - mu*mu + 1e-5f);
        }
    }
    __syncthreads();
    for (int idx = tid; idx < cnt*RK; idx += 256){
        int j = idx >> 9, f = idx & (RK-1);
        float v = (hs[j][f] - mu9[j])*rs9[j]*gam1[f] + bet1[f];
        hs[j][f] = fmaxf(v, 0.f)*onrm[lid[j]];
    }
    __syncthreads();
    const float in0 = ideg[0] ? rsqrtf((float)ideg[0]) : 1.0f;
    float* dst = g_mc + (size_t)g*RK;
    for (int c4 = tid; c4 < RK/4; c4 += 256){
        const int k0 = ((c4 >> 1) << 3) + ((c4 & 1) << 1);
        const int ks[4] = {k0, k0+4, k0+1, k0+5};
        float4 v; float* vp = &v.x;
        #pragma unroll
        for (int q = 0; q < 4; q++){
            float val = 0.f;
            #pragma unroll
            for (int e = 0; e < EPG; e++)
                if (dl[e] == 0) val += hs[n2r[sl[e]]][ks[q]];
            vp[q] = tf32r(val*in0);
        }
        ((float4*)dst)[c4] = v;
    }
}

// ------------- TF32 GEMM: C = A @ W^T, optional row-count early exit ---------
#define BM 128
#define BN 256
#define BK 32
#define APITCH 40
#define BPITCH 40
#define STAGES 3
#define STG_F (BM*APITCH + BN*BPITCH)
#define SMEM_GEMM (STAGES*STG_F*4)

__global__ __launch_bounds__(256,1) void gemm_tf32_kernel(
    const float* __restrict__ A, const float* __restrict__ Wt,
    float* __restrict__ C, const int* __restrict__ tot)
{
    extern __shared__ float smbuf[];
    const int bn = blockIdx.x, bm = blockIdx.y;
    if (tot && bm*BM >= *tot) return;
    const int tid = threadIdx.x;
    const int lane = tid & 31, warp = tid >> 5;
    const int wm = warp & 1, wn = warp >> 1;
    const int gid = lane >> 2, tig = lane & 3;

    float c[4][8][4];
    #pragma unroll
    for (int mt = 0; mt < 4; mt++)
        #pragma unroll
        for (int nf = 0; nf < 8; nf++)
            #pragma unroll
            for (int q = 0; q < 4; q++) c[mt][nf][q] = 0.f;

    const float* Ag = A  + (size_t)bm*BM*RK;
    const float* Bg = Wt + (size_t)bn*BN*RK;

    auto fill = [&](int t){
        float* As = smbuf + (t % STAGES)*STG_F;
        float* Bs = As + BM*APITCH;
        const int k0 = t*BK;
        #pragma unroll
        for (int i = 0; i < 4; i++){
            int idx = tid + i*256; int r = idx >> 3, cc = idx & 7;
            cp_async16(&As[r*APITCH + cc*4], Ag + (size_t)r*RK + k0 + cc*4);
        }
        #pragma unroll
        for (int i = 0; i < 8; i++){
            int idx = tid + i*256; int r = idx >> 3, cc = idx & 7;
            cp_async16(&Bs[r*BPITCH + cc*4], Bg + (size_t)r*RK + k0 + cc*4);
        }
        cp_commit();
    };

    fill(0); fill(1);

    #pragma unroll 1
    for (int kt = 0; kt < RK/BK; kt++){
        cp_wait<1>();
        __syncthreads();
        if (kt + 2 < RK/BK) fill(kt + 2);
        else cp_commit();

        const float* Ac = smbuf + (kt % STAGES)*STG_F;
        const float* Bc = Ac + BM*APITCH;
        #pragma unroll
        for (int ks = 0; ks < BK/8; ks++){
            const int kp = ks*8 + 2*tig;
            unsigned a[4][4]; unsigned b[8][2];
            #pragma unroll
            for (int mt = 0; mt < 4; mt++){
                int r = wm*64 + mt*16 + gid;
                float2 p0 = *(const float2*)&Ac[ r    *APITCH + kp];
                float2 p1 = *(const float2*)&Ac[(r+8) *APITCH + kp];
                a[mt][0] = __float_as_uint(p0.x);
                a[mt][1] = __float_as_uint(p1.x);
                a[mt][2] = __float_as_uint(p0.y);
                a[mt][3] = __float_as_uint(p1.y);
            }
            #pragma unroll
            for (int nf = 0; nf < 8; nf++){
                int cn = wn*64 + nf*8 + gid;
                float2 pb = *(const float2*)&Bc[cn*BPITCH + kp];
                b[nf][0] = __float_as_uint(pb.x);
                b[nf][1] = __float_as_uint(pb.y);
            }
            #pragma unroll
            for (int mt = 0; mt < 4; mt++)
                #pragma unroll
                for (int nf = 0; nf < 8; nf++)
                    mma_tf32(c[mt][nf], a[mt], b[nf]);
        }
    }
    #pragma unroll
    for (int mt = 0; mt < 4; mt++){
        int r = bm*BM + wm*64 + mt*16 + gid;
        #pragma unroll
        for (int nf = 0; nf < 8; nf++){
            int cn = bn*BN + wn*64 + nf*8 + tig*2;
            *(float2*)&C[(size_t)r*RK + cn]     = make_float2(c[mt][nf][0], c[mt][nf][1]);
            *(float2*)&C[(size_t)(r+8)*RK + cn] = make_float2(c[mt][nf][2], c[mt][nf][3]);
        }
    }
}

// ---------------- output head ------------------------------------------------
__global__ __launch_bounds__(256) void out_kernel(
    const float* __restrict__ bias, const float* __restrict__ gamma,
    const float* __restrict__ beta, const float* __restrict__ wout,
    const float* __restrict__ bout, float* __restrict__ out)
{
    const int g = blockIdx.x*8 + (threadIdx.x >> 5);
    const int ln = threadIdx.x & 31;
    const float* row = g_hc + (size_t)g*RK;
    float v[16]; float s = 0.f, ss = 0.f;
    #pragma unroll
    for (int j = 0; j < 16; j++){
        int f = ln + j*32;
        float x = row[f] + bias[f];
        v[j] = x; s += x; ss += x*x;
    }
    s = wredsum(s); ss = wredsum(ss);
    float mu = s*(1.0f/RK);
    float rs = rsqrtf(ss*(1.0f/RK) - mu*mu + 1e-5f);
    float dot = 0.f;
    #pragma unroll
    for (int j = 0; j < 16; j++){
        int f = ln + j*32;
        float y = fmaxf((v[j]-mu)*rs*gamma[f] + beta[f], 0.f);
        dot += y*wout[f];
    }
    dot = wredsum(dot);
    if (ln == 0) out[g] = dot + bout[0];
}

// ---------------- launcher ---------------------------------------------------
extern "C" void kernel_launch(void* const* d_in, const int* in_sizes, int n_in,
                              void* d_out, int out_size){
    (void)in_sizes; (void)n_in; (void)out_size;
    const void*  feat = d_in[0];
    const void*  src  = d_in[1];
    const void*  dst  = d_in[2];
    const float* emb  = (const float*)d_in[3];
    const float* Ws   = (const float*)d_in[4];
    const float* bs   = (const float*)d_in[5];
    const float* gam  = (const float*)d_in[6];
    const float* bet  = (const float*)d_in[7];
    const float* wout = (const float*)d_in[8];
    const float* bout = (const float*)d_in[9];
    float* out = (float*)d_out;

    cudaFuncSetAttribute(gemm_tf32_kernel,
                         cudaFuncAttributeMaxDynamicSharedMemorySize, SMEM_GEMM);

    float* gm;  cudaGetSymbolAddress((void**)&gm,  g_m);
    float* gh;  cudaGetSymbolAddress((void**)&gh,  g_h);
    float* gmc; cudaGetSymbolAddress((void**)&gmc, g_mc);
    float* ghc; cudaGetSymbolAddress((void**)&ghc, g_hc);
    float* gwt; cudaGetSymbolAddress((void**)&gwt, g_Wt);
    int*   gtot; cudaGetSymbolAddress((void**)&gtot, g_total);

    detect_kernel<<<1, 32>>>((const int*)src, (const int*)feat);
    round_w_kernel<<<dim3(16,16,3), dim3(32,8)>>>(Ws);
    ew0_kernel<<<dim3(VOC,2), 256>>>(emb, Ws);
    cnt_kernel<<<NB/256, 256>>>(src, dst);
    scan_kernel<<<1, 1024>>>();

    fuse1_kernel<<<NB, 256>>>(feat, src, dst, bs, gam, bet);
    dim3 gg(RK/BN, NN/BM);                 // (2, 1152) worst case; early exit
    gemm_tf32_kernel<<<gg, 256, SMEM_GEMM>>>(gm, gwt + RK*RK, gh, gtot);
    fuseD_kernel<<<NB, 256>>>(src, dst, bs + RK, gam + RK, bet + RK);
    dim3 gc(RK/BN, NB/BM);                 // (2, 128)
    gemm_tf32_kernel<<<gc, 256, SMEM_GEMM>>>(gmc, gwt + 2*RK*RK, ghc, nullptr);
    out_kernel<<<NB/8, 256>>>(bs + 2*RK, gam + 2*RK, bet + 2*RK, wout, bout, out);
}